// round 3
// baseline (speedup 1.0000x reference)
#include <cuda_runtime.h>
#include <cuda_fp16.h>
#include <cstdint>
#include <cstddef>

#define B_    2
#define L_    192
#define H_    512
#define NH_   8
#define ML_   (B_*L_)     // 384 rows (b,l) flattened
#define TROWS_ 383        // distinct position diffs: [-191, 191]

// ---------------- scratch (device globals; no allocation allowed) ----------------
static __device__ __align__(16) __half d_Th[4 * TROWS_ * H_];   // 4 pe tables (half)
static __device__ __align__(16) float  d_kproj[ML_ * H_];
static __device__ __align__(16) float  d_qkA[ML_ * H_];         // qproj + bq + u_bias (A' for qk GEMM)
static __device__ __align__(16) float  d_u[ML_ * H_];           // qproj + bq + v_bias
static __device__ __align__(16) __half d_vh[ML_ * H_];          // v projection (half)
static __device__ __align__(16) __half d_gh[ML_ * NH_ * H_];    // u_head @ Wr_head (half)
static __device__ __align__(16) float  d_qk[2 * NH_ * L_ * L_]; // per-head (q+u_bias).k scores
static __device__ __align__(16) float  d_attnout[ML_ * H_];

__device__ __forceinline__ float st_conv(float v, float*)  { return v; }
__device__ __forceinline__ __half st_conv(float v, __half*) { return __float2half(v); }

// ---------------- tiled SGEMM: 32(M) x 64(N) tile, BK=16, 2x4 microtile ----------
// TRANSB=true : C[m,n] = sum_k A[m*lda+k] * B[n*ldb+k]
// TRANSB=false: C[m,n] = sum_k A[m*lda+k] * B[k*ldb+n]
// Optional second output C2 = acc + bias + add2 (while C = acc + bias + addA).
template<bool TRANSB, typename OT>
__device__ __forceinline__ void gemm_tile(
    const float* __restrict__ A, int lda,
    const float* __restrict__ B, int ldb,
    const float* __restrict__ bias,
    OT* __restrict__ C, int ldc,
    int M, int N, int K,
    const float* __restrict__ addA = nullptr,
    float* __restrict__ C2 = nullptr,
    const float* __restrict__ add2 = nullptr)
{
    __shared__ float As[16][34];
    __shared__ float Bs[16][68];
    const int tid = threadIdx.x;
    const int tx = tid & 15, ty = tid >> 4;
    const int m0 = blockIdx.y * 32, n0 = blockIdx.x * 64;
    float acc[2][4];
#pragma unroll
    for (int i = 0; i < 2; ++i)
#pragma unroll
        for (int j = 0; j < 4; ++j) acc[i][j] = 0.f;

    const int alm = tid >> 3;          // 0..31 (A row in tile)
    const int alk = (tid & 7) * 2;     // 0..14 (A k pair)
    const int blm = tid >> 2;          // 0..63 (B "row" for TRANSB)
    const int blk = (tid & 3) * 4;     // 0..12

    for (int k0 = 0; k0 < K; k0 += 16) {
        float2 av = make_float2(0.f, 0.f);
        if (m0 + alm < M)
            av = *reinterpret_cast<const float2*>(A + (size_t)(m0 + alm) * lda + k0 + alk);
        As[alk + 0][alm] = av.x; As[alk + 1][alm] = av.y;
        if (TRANSB) {
            float4 bv = make_float4(0.f, 0.f, 0.f, 0.f);
            if (n0 + blm < N)
                bv = *reinterpret_cast<const float4*>(B + (size_t)(n0 + blm) * ldb + k0 + blk);
            Bs[blk + 0][blm] = bv.x; Bs[blk + 1][blm] = bv.y;
            Bs[blk + 2][blm] = bv.z; Bs[blk + 3][blm] = bv.w;
        } else {
            const int bk = tid >> 4;          // 0..15
            const int bn = (tid & 15) * 4;    // 0..60
            float4 bv = make_float4(0.f, 0.f, 0.f, 0.f);
            if (n0 + bn < N)
                bv = *reinterpret_cast<const float4*>(B + (size_t)(k0 + bk) * ldb + n0 + bn);
            *reinterpret_cast<float4*>(&Bs[bk][bn]) = bv;
        }
        __syncthreads();
#pragma unroll
        for (int kk = 0; kk < 16; ++kk) {
            float a0 = As[kk][ty * 2 + 0];
            float a1 = As[kk][ty * 2 + 1];
            float bb[4];
#pragma unroll
            for (int j = 0; j < 4; ++j) bb[j] = Bs[kk][tx * 4 + j];
#pragma unroll
            for (int j = 0; j < 4; ++j) { acc[0][j] += a0 * bb[j]; acc[1][j] += a1 * bb[j]; }
        }
        __syncthreads();
    }
    const int mo = m0 + ty * 2, no = n0 + tx * 4;
#pragma unroll
    for (int i = 0; i < 2; ++i) {
        if (mo + i < M) {
#pragma unroll
            for (int j = 0; j < 4; ++j) {
                if (no + j < N) {
                    float base = acc[i][j];
                    if (bias) base += bias[no + j];
                    float v1 = base;
                    if (addA) v1 += addA[no + j];
                    C[(size_t)(mo + i) * ldc + no + j] = st_conv(v1, (OT*)nullptr);
                    if (C2) C2[(size_t)(mo + i) * ldc + no + j] = base + add2[no + j];
                }
            }
        }
    }
}

// ---------------- stage 1: projections + pe tables (fused launch) ----------------
__global__ void __launch_bounds__(256) k_pre(
    const float* __restrict__ key, const float* __restrict__ query, const float* __restrict__ value,
    const float* __restrict__ Wk, const float* __restrict__ bk,
    const float* __restrict__ Wq, const float* __restrict__ bq,
    const float* __restrict__ Wv, const float* __restrict__ bv,
    const float* __restrict__ pe, const float* __restrict__ W_fus,
    const float* __restrict__ u_bias, const float* __restrict__ v_bias)
{
    const int z = blockIdx.z;
    if (z == 0) {
        gemm_tile<true>(key, H_, Wk, H_, bk, d_kproj, H_, ML_, H_, H_);
    } else if (z == 1) {
        // dual write: d_qkA = q@Wq^T + bq + u_bias ; d_u = q@Wq^T + bq + v_bias
        gemm_tile<true>(query, H_, Wq, H_, bq, d_qkA, H_, ML_, H_, H_,
                        u_bias, d_u, v_bias);
    } else if (z == 2) {
        gemm_tile<true>(value, H_, Wv, H_, bv, d_vh, H_, ML_, H_, H_);
    } else {
        const int t = z - 3;   // table 0..3
        gemm_tile<true>(pe + 321 * H_, H_, W_fus + t * 256, 2 * H_, nullptr,
                        d_Th + (size_t)t * TROWS_ * H_, H_, TROWS_, H_, 256);
    }
}

// ---------------- stage 2: g (half) + per-head qk GEMMs (fused launch) ----------------
__global__ void __launch_bounds__(256) k_gqk(const float* __restrict__ Wr)
{
    const int z = blockIdx.z;
    if (z < 8) {
        // g[m, z, f] = sum_d u[m, z*64+d] * Wr[z*64+d, f]
        gemm_tile<false>(d_u + z * 64, H_, Wr + (size_t)z * 64 * H_, H_, nullptr,
                         d_gh + (size_t)z * H_, NH_ * H_, ML_, H_, 64);
    } else {
        if (blockIdx.x >= 3 || blockIdx.y >= 6) return;
        const int idx = z - 8;         // b*8 + n
        const int b = idx >> 3, n = idx & 7;
        gemm_tile<true>(d_qkA  + (size_t)b * L_ * H_ + n * 64, H_,
                        d_kproj + (size_t)b * L_ * H_ + n * 64, H_, nullptr,
                        d_qk + (size_t)idx * L_ * L_, L_, L_, L_, 64);
    }
}

__device__ __forceinline__ __half2 shfl_xor_h2(__half2 v, int s) {
    unsigned u = *reinterpret_cast<unsigned*>(&v);
    u = __shfl_xor_sync(0xffffffffu, u, s);
    return *reinterpret_cast<__half2*>(&u);
}

// ---------------- stage 3: fused rel-scores + softmax + attn@V per (b,q) ----------------
__global__ void __launch_bounds__(256, 3) k_attn(
    const float* __restrict__ b_fus,
    const int* __restrict__ pos_s,
    const int* __restrict__ pos_e,
    const int* __restrict__ seq_len)
{
    __shared__ __align__(16) __half g_s[NH_][H_];    // 8 KB
    __shared__ __align__(16) float sc[NH_][L_];      // 6 KB : init = qk score, then probs
    __shared__ int ksp[L_], kep[L_];

    const int m = blockIdx.x;          // b*L + q
    const int b = m / L_;
    const int qi = m % L_;
    const int tid = threadIdx.x;
    const int lane = tid & 31;
    const int warp = tid >> 5;

    // g tile (half): 4096 halves = 512 uint4
    {
        const uint4* src = reinterpret_cast<const uint4*>(d_gh + (size_t)m * (NH_ * H_));
        uint4* dst = reinterpret_cast<uint4*>(&g_s[0][0]);
        for (int i = tid; i < (NH_ * H_) / 8; i += 256) dst[i] = src[i];
    }
    // sc init = qk (A' already includes the C term via folded u_bias)
    for (int i = tid; i < NH_ * L_; i += 256) {
        const int n = i / L_, k = i % L_;
        sc[n][k] = d_qk[((size_t)(b * NH_ + n) * L_ + qi) * L_ + k];
    }
    for (int i = tid; i < L_; i += 256) { ksp[i] = pos_s[b * L_ + i]; kep[i] = pos_e[b * L_ + i]; }
    const int psq = pos_s[m], peq = pos_e[m];
    const int slen = seq_len[b];

    // b_fus -> half2 regs for this lane's dims: h = lane*8 + ci*256
    __half2 bfh[2][4];
#pragma unroll
    for (int ci = 0; ci < 2; ++ci) {
        const int h = lane * 8 + ci * 256;
        float4 f0 = *reinterpret_cast<const float4*>(b_fus + h);
        float4 f1 = *reinterpret_cast<const float4*>(b_fus + h + 4);
        bfh[ci][0] = __floats2half2_rn(f0.x, f0.y);
        bfh[ci][1] = __floats2half2_rn(f0.z, f0.w);
        bfh[ci][2] = __floats2half2_rn(f1.x, f1.y);
        bfh[ci][3] = __floats2half2_rn(f1.z, f1.w);
    }
    __syncthreads();

    const __half2 hz = __float2half2_rn(0.f);
    const __half* __restrict__ T = d_Th;
    const int lane8 = lane << 3;       // half offset within 512-half row (ci=0)

    // --- software-pipelined score loop: warp w handles keys w, w+8, ... ---
    int o0, o1, o2, o3;                // half offsets of 4 table rows for current key
    {
        const int kk = warp;
        o0 = ((0 * TROWS_ + psq - ksp[kk] + 191) << 9);
        o1 = ((1 * TROWS_ + psq - kep[kk] + 191) << 9);
        o2 = ((2 * TROWS_ + peq - ksp[kk] + 191) << 9);
        o3 = ((3 * TROWS_ + peq - kep[kk] + 191) << 9);
    }
    uint4 A0 = *reinterpret_cast<const uint4*>(T + o0 + lane8);
    uint4 A1 = *reinterpret_cast<const uint4*>(T + o1 + lane8);
    uint4 A2 = *reinterpret_cast<const uint4*>(T + o2 + lane8);
    uint4 A3 = *reinterpret_cast<const uint4*>(T + o3 + lane8);

    int kk = warp;
#pragma unroll 1
    for (int t = 0; t < 24; ++t) {
        __half2 acc[NH_];
#pragma unroll
        for (int n = 0; n < NH_; ++n) acc[n] = hz;

        // prefetch second half of current key (ci=1)
        uint4 B0 = *reinterpret_cast<const uint4*>(T + o0 + lane8 + 256);
        uint4 B1 = *reinterpret_cast<const uint4*>(T + o1 + lane8 + 256);
        uint4 B2 = *reinterpret_cast<const uint4*>(T + o2 + lane8 + 256);
        uint4 B3 = *reinterpret_cast<const uint4*>(T + o3 + lane8 + 256);

        // compute ci=0 from A*
        {
            const __half2* c0 = reinterpret_cast<const __half2*>(&A0);
            const __half2* c1 = reinterpret_cast<const __half2*>(&A1);
            const __half2* c2 = reinterpret_cast<const __half2*>(&A2);
            const __half2* c3 = reinterpret_cast<const __half2*>(&A3);
            __half2 r[4];
#pragma unroll
            for (int j = 0; j < 4; ++j) {
                __half2 s = __hadd2(__hadd2(c0[j], c1[j]), __hadd2(c2[j], c3[j]));
                r[j] = __hmax2(__hadd2(s, bfh[0][j]), hz);
            }
            const int h = lane8;
#pragma unroll
            for (int n = 0; n < NH_; ++n) {
                uint4 gg = *reinterpret_cast<const uint4*>(&g_s[n][h]);
                const __half2* gh = reinterpret_cast<const __half2*>(&gg);
#pragma unroll
                for (int j = 0; j < 4; ++j) acc[n] = __hfma2(gh[j], r[j], acc[n]);
            }
        }

        // prefetch first half of NEXT key (ci=0)
        if (t < 23) {
            const int kn = kk + 8;
            o0 = ((0 * TROWS_ + psq - ksp[kn] + 191) << 9);
            o1 = ((1 * TROWS_ + psq - kep[kn] + 191) << 9);
            o2 = ((2 * TROWS_ + peq - ksp[kn] + 191) << 9);
            o3 = ((3 * TROWS_ + peq - kep[kn] + 191) << 9);
            A0 = *reinterpret_cast<const uint4*>(T + o0 + lane8);
            A1 = *reinterpret_cast<const uint4*>(T + o1 + lane8);
            A2 = *reinterpret_cast<const uint4*>(T + o2 + lane8);
            A3 = *reinterpret_cast<const uint4*>(T + o3 + lane8);
        }

        // compute ci=1 from B*
        {
            const __half2* c0 = reinterpret_cast<const __half2*>(&B0);
            const __half2* c1 = reinterpret_cast<const __half2*>(&B1);
            const __half2* c2 = reinterpret_cast<const __half2*>(&B2);
            const __half2* c3 = reinterpret_cast<const __half2*>(&B3);
            __half2 r[4];
#pragma unroll
            for (int j = 0; j < 4; ++j) {
                __half2 s = __hadd2(__hadd2(c0[j], c1[j]), __hadd2(c2[j], c3[j]));
                r[j] = __hmax2(__hadd2(s, bfh[1][j]), hz);
            }
            const int h = lane8 + 256;
#pragma unroll
            for (int n = 0; n < NH_; ++n) {
                uint4 gg = *reinterpret_cast<const uint4*>(&g_s[n][h]);
                const __half2* gh = reinterpret_cast<const __half2*>(&gg);
#pragma unroll
                for (int j = 0; j < 4; ++j) acc[n] = __hfma2(gh[j], r[j], acc[n]);
            }
        }

        // butterfly reduce (half2 carries 2 partial sums per shuffle)
#pragma unroll
        for (int s = 16; s > 0; s >>= 1) {
#pragma unroll
            for (int n = 0; n < NH_; ++n) acc[n] = __hadd2(acc[n], shfl_xor_h2(acc[n], s));
        }
        if (lane == 0) {
            const bool valid = kk < slen;
#pragma unroll
            for (int n = 0; n < NH_; ++n) {
                float bd = __low2float(acc[n]) + __high2float(acc[n]);
                float v = (sc[n][kk] + bd) * 0.125f;
                sc[n][kk] = valid ? v : -1e30f;
            }
        }
        kk += 8;
    }
    __syncthreads();

    // softmax over k, warp = head
    {
        const int n = warp;
        float mx = -3.4e38f;
#pragma unroll
        for (int j = 0; j < 6; ++j) mx = fmaxf(mx, sc[n][lane + 32 * j]);
#pragma unroll
        for (int s = 16; s > 0; s >>= 1) mx = fmaxf(mx, __shfl_xor_sync(0xffffffffu, mx, s));
        float sum = 0.f;
        float ev[6];
#pragma unroll
        for (int j = 0; j < 6; ++j) {
            ev[j] = __expf(sc[n][lane + 32 * j] - mx);
            sum += ev[j];
        }
#pragma unroll
        for (int s = 16; s > 0; s >>= 1) sum += __shfl_xor_sync(0xffffffffu, sum, s);
        const float inv = 1.f / sum;
#pragma unroll
        for (int j = 0; j < 6; ++j) sc[n][lane + 32 * j] = ev[j] * inv;
    }
    __syncthreads();

    // out[m, h] = sum_k attn[n,k] * v_half[b,k,h]   (n = warp for h = 2*tid)
    {
        const __half* __restrict__ vb = d_vh + (size_t)b * L_ * H_;
        const int h = tid * 2;
        const int n = warp;
        float o0a = 0.f, o1a = 0.f, o0b = 0.f, o1b = 0.f;
#pragma unroll 4
        for (int k = 0; k < L_; k += 2) {
            const float a0 = sc[n][k], a1 = sc[n][k + 1];
            __half2 v0 = *reinterpret_cast<const __half2*>(vb + (size_t)k * H_ + h);
            __half2 v1 = *reinterpret_cast<const __half2*>(vb + (size_t)(k + 1) * H_ + h);
            float2 f0 = __half22float2(v0);
            float2 f1 = __half22float2(v1);
            o0a += a0 * f0.x; o1a += a0 * f0.y;
            o0b += a1 * f1.x; o1b += a1 * f1.y;
        }
        d_attnout[(size_t)m * H_ + h]     = o0a + o0b;
        d_attnout[(size_t)m * H_ + h + 1] = o1a + o1b;
    }
}

// ---------------- stage 4: output projection ----------------
__global__ void __launch_bounds__(256) k_ff(const float* __restrict__ Wff,
                                            const float* __restrict__ bff,
                                            float* __restrict__ out)
{
    gemm_tile<true>(d_attnout, H_, Wff, H_, bff, out, H_, ML_, H_, H_);
}

// ---------------- launch ----------------
extern "C" void kernel_launch(void* const* d_in, const int* in_sizes, int n_in,
                              void* d_out, int out_size)
{
    (void)n_in; (void)out_size;
    const float* key     = (const float*)d_in[0];
    const float* query   = (const float*)d_in[1];
    const float* value   = (const float*)d_in[2];
    const int*   seq_len = (const int*)d_in[3];
    const int ip = (in_sizes[4] == 1) ? 5 : 4;   // skip lex_num if present
    const int*   pos_s  = (const int*)d_in[ip + 0];
    const int*   pos_e  = (const int*)d_in[ip + 1];
    const float* pe     = (const float*)d_in[ip + 2];
    const float* W_fus  = (const float*)d_in[ip + 3];
    const float* b_fus  = (const float*)d_in[ip + 4];
    const float* Wk     = (const float*)d_in[ip + 5];
    const float* bk     = (const float*)d_in[ip + 6];
    const float* Wq     = (const float*)d_in[ip + 7];
    const float* bq     = (const float*)d_in[ip + 8];
    const float* Wv     = (const float*)d_in[ip + 9];
    const float* bv     = (const float*)d_in[ip + 10];
    const float* Wr     = (const float*)d_in[ip + 11];
    const float* br     = (const float*)d_in[ip + 12];  // dropped: constant over k under softmax
    const float* u_bias = (const float*)d_in[ip + 13];
    const float* v_bias = (const float*)d_in[ip + 14];
    const float* Wff    = (const float*)d_in[ip + 15];
    const float* bff    = (const float*)d_in[ip + 16];
    (void)br;

    k_pre  <<<dim3(8, 12, 7), 256>>>(key, query, value, Wk, bk, Wq, bq, Wv, bv,
                                     pe, W_fus, u_bias, v_bias);
    k_gqk  <<<dim3(8, 12, 24), 256>>>(Wr);
    k_attn <<<ML_, 256>>>(b_fus, pos_s, pos_e, seq_len);
    k_ff   <<<dim3(8, 12, 1), 256>>>(Wff, bff, (float*)d_out);
}

// round 4
// speedup vs baseline: 1.1449x; 1.1449x over previous
#include <cuda_runtime.h>
#include <cuda_fp16.h>
#include <cstdint>
#include <cstddef>

#define B_    2
#define L_    192
#define H_    512
#define NH_   8
#define ML_   (B_*L_)     // 384 rows (b,l) flattened
#define TROWS_ 383        // distinct position diffs: [-191, 191]

// ---------------- scratch (device globals; no allocation allowed) ----------------
static __device__ __align__(16) __half d_Th[4 * TROWS_ * H_];   // 4 pe tables (half)
static __device__ __align__(16) float  d_kproj[ML_ * H_];
static __device__ __align__(16) float  d_qkA[ML_ * H_];         // qproj + bq + u_bias
static __device__ __align__(16) float  d_u[ML_ * H_];           // qproj + bq + v_bias
static __device__ __align__(16) __half d_vh[ML_ * H_];          // v projection (half)
static __device__ __align__(16) __half d_gh[ML_ * NH_ * H_];    // u_head @ Wr_head (half)
static __device__ __align__(16) float  d_qk[2 * NH_ * L_ * L_]; // per-head (q+u_bias).k
static __device__ __align__(16) float  d_attnout[ML_ * H_];

__device__ __forceinline__ float st_conv(float v, float*)  { return v; }
__device__ __forceinline__ __half st_conv(float v, __half*) { return __float2half(v); }

// ------- tiled SGEMM: 64x64 tile, BK=16, 4x4 microtile, DOUBLE-BUFFERED smem -------
// TRANSB=true : C[m,n] = sum_k A[m*lda+k] * B[n*ldb+k]
// TRANSB=false: C[m,n] = sum_k A[m*lda+k] * B[k*ldb+n]
// ATOMIC: epilogue does atomicAdd into C (fp32 only).
// Optional dual output: C = acc+bias+addA ; C2 = acc+bias+add2.
template<bool TRANSB, bool ATOMIC, typename OT>
__device__ __forceinline__ void gemm_tile(
    const float* __restrict__ A, int lda,
    const float* __restrict__ B, int ldb,
    const float* __restrict__ bias,
    OT* __restrict__ C, int ldc,
    int M, int N, int K,
    const float* __restrict__ addA = nullptr,
    float* __restrict__ C2 = nullptr,
    const float* __restrict__ add2 = nullptr)
{
    __shared__ float As[2][16][68];
    __shared__ float Bs[2][16][68];
    const int tid = threadIdx.x;
    const int tx = tid & 15, ty = tid >> 4;
    const int m0 = blockIdx.y * 64, n0 = blockIdx.x * 64;
    float acc[4][4];
#pragma unroll
    for (int i = 0; i < 4; ++i)
#pragma unroll
        for (int j = 0; j < 4; ++j) acc[i][j] = 0.f;

    const int lm = tid >> 2;          // 0..63 (row within tile for A / TRANSB-B)
    const int lk = (tid & 3) * 4;     // 0,4,8,12
    const int bk = tid >> 4;          // 0..15 (NN B)
    const int bn = (tid & 15) * 4;    // 0..60

    // ---- prologue: tile 0 -> buffer 0 ----
    {
        float4 av = make_float4(0.f, 0.f, 0.f, 0.f);
        if (m0 + lm < M)
            av = *reinterpret_cast<const float4*>(A + (size_t)(m0 + lm) * lda + lk);
        As[0][lk + 0][lm] = av.x; As[0][lk + 1][lm] = av.y;
        As[0][lk + 2][lm] = av.z; As[0][lk + 3][lm] = av.w;
        if (TRANSB) {
            float4 bv = make_float4(0.f, 0.f, 0.f, 0.f);
            if (n0 + lm < N)
                bv = *reinterpret_cast<const float4*>(B + (size_t)(n0 + lm) * ldb + lk);
            Bs[0][lk + 0][lm] = bv.x; Bs[0][lk + 1][lm] = bv.y;
            Bs[0][lk + 2][lm] = bv.z; Bs[0][lk + 3][lm] = bv.w;
        } else {
            float4 bv = make_float4(0.f, 0.f, 0.f, 0.f);
            if (n0 + bn < N)
                bv = *reinterpret_cast<const float4*>(B + (size_t)bk * ldb + n0 + bn);
            *reinterpret_cast<float4*>(&Bs[0][bk][bn]) = bv;
        }
    }
    __syncthreads();

    int buf = 0;
    for (int k0 = 0; k0 < K; k0 += 16) {
        const bool has_next = (k0 + 16 < K);
        float4 av = make_float4(0.f, 0.f, 0.f, 0.f);
        float4 bv = make_float4(0.f, 0.f, 0.f, 0.f);
        if (has_next) {
            const int kn = k0 + 16;
            if (m0 + lm < M)
                av = *reinterpret_cast<const float4*>(A + (size_t)(m0 + lm) * lda + kn + lk);
            if (TRANSB) {
                if (n0 + lm < N)
                    bv = *reinterpret_cast<const float4*>(B + (size_t)(n0 + lm) * ldb + kn + lk);
            } else {
                if (n0 + bn < N)
                    bv = *reinterpret_cast<const float4*>(B + (size_t)(kn + bk) * ldb + n0 + bn);
            }
        }
        // compute from current buffer (covers the in-flight global loads)
#pragma unroll
        for (int kk = 0; kk < 16; ++kk) {
            float a[4], bb[4];
#pragma unroll
            for (int i = 0; i < 4; ++i) a[i] = As[buf][kk][ty * 4 + i];
#pragma unroll
            for (int j = 0; j < 4; ++j) bb[j] = Bs[buf][kk][tx * 4 + j];
#pragma unroll
            for (int i = 0; i < 4; ++i)
#pragma unroll
                for (int j = 0; j < 4; ++j) acc[i][j] += a[i] * bb[j];
        }
        // store prefetched tile into the other buffer (not being read this iter)
        if (has_next) {
            const int nb = buf ^ 1;
            As[nb][lk + 0][lm] = av.x; As[nb][lk + 1][lm] = av.y;
            As[nb][lk + 2][lm] = av.z; As[nb][lk + 3][lm] = av.w;
            if (TRANSB) {
                Bs[nb][lk + 0][lm] = bv.x; Bs[nb][lk + 1][lm] = bv.y;
                Bs[nb][lk + 2][lm] = bv.z; Bs[nb][lk + 3][lm] = bv.w;
            } else {
                *reinterpret_cast<float4*>(&Bs[nb][bk][bn]) = bv;
            }
        }
        __syncthreads();
        buf ^= 1;
    }

    const int mo = m0 + ty * 4, no = n0 + tx * 4;
#pragma unroll
    for (int i = 0; i < 4; ++i) {
        if (mo + i < M) {
#pragma unroll
            for (int j = 0; j < 4; ++j) {
                if (no + j < N) {
                    float base = acc[i][j];
                    if (bias) base += bias[no + j];
                    if (ATOMIC) {
                        atomicAdd(reinterpret_cast<float*>(&C[(size_t)(mo + i) * ldc + no + j]), base);
                    } else {
                        float v1 = base;
                        if (addA) v1 += addA[no + j];
                        C[(size_t)(mo + i) * ldc + no + j] = st_conv(v1, (OT*)nullptr);
                        if (C2) C2[(size_t)(mo + i) * ldc + no + j] = base + add2[no + j];
                    }
                }
            }
        }
    }
}

// ---------------- stage 1: projections + pe tables (fused launch) ----------------
__global__ void __launch_bounds__(256) k_pre(
    const float* __restrict__ key, const float* __restrict__ query, const float* __restrict__ value,
    const float* __restrict__ Wk, const float* __restrict__ bk,
    const float* __restrict__ Wq, const float* __restrict__ bq,
    const float* __restrict__ Wv, const float* __restrict__ bv,
    const float* __restrict__ pe, const float* __restrict__ W_fus,
    const float* __restrict__ u_bias, const float* __restrict__ v_bias)
{
    const int z = blockIdx.z;
    if (z == 0) {
        gemm_tile<true, false>(key, H_, Wk, H_, bk, d_kproj, H_, ML_, H_, H_);
    } else if (z == 1) {
        // dual write: d_qkA = q@Wq^T + bq + u_bias ; d_u = q@Wq^T + bq + v_bias
        gemm_tile<true, false>(query, H_, Wq, H_, bq, d_qkA, H_, ML_, H_, H_,
                               u_bias, d_u, v_bias);
    } else if (z == 2) {
        gemm_tile<true, false>(value, H_, Wv, H_, bv, d_vh, H_, ML_, H_, H_);
    } else {
        const int t = z - 3;   // table 0..3
        gemm_tile<true, false>(pe + 321 * H_, H_, W_fus + t * 256, 2 * H_, nullptr,
                               d_Th + (size_t)t * TROWS_ * H_, H_, TROWS_, H_, 256);
    }
}

// -------- stage 2: g (half) + per-head qk GEMMs + early zero of d_out --------
__global__ void __launch_bounds__(256) k_gqk(const float* __restrict__ Wr,
                                             float* __restrict__ out)
{
    const int z = blockIdx.z;
    if (z < 8) {
        // g[m, z, f] = sum_d u[m, z*64+d] * Wr[z*64+d, f]
        gemm_tile<false, false>(d_u + z * 64, H_, Wr + (size_t)z * 64 * H_, H_, nullptr,
                                d_gh + (size_t)z * H_, NH_ * H_, ML_, H_, 64);
    } else if (z < 24) {
        if (blockIdx.x >= 3 || blockIdx.y >= 3) return;
        const int idx = z - 8;         // b*8 + n
        const int b = idx >> 3, n = idx & 7;
        gemm_tile<true, false>(d_qkA   + (size_t)b * L_ * H_ + n * 64, H_,
                               d_kproj + (size_t)b * L_ * H_ + n * 64, H_, nullptr,
                               d_qk + (size_t)idx * L_ * L_, L_, L_, L_, 64);
    } else {
        // zero d_out for k_ff's atomic accumulation (runs well before k_ff)
        const float4 z4 = make_float4(0.f, 0.f, 0.f, 0.f);
        float4* o4 = reinterpret_cast<float4*>(out);
        const int stride = 48 * 256;   // blocks(8x6) * 256 threads
        const int start = (blockIdx.y * 8 + blockIdx.x) * 256 + threadIdx.x;
        for (int i = start; i < (ML_ * H_) / 4; i += stride) o4[i] = z4;
    }
}

__device__ __forceinline__ __half2 shfl_xor_h2(__half2 v, int s) {
    unsigned u = *reinterpret_cast<unsigned*>(&v);
    u = __shfl_xor_sync(0xffffffffu, u, s);
    return *reinterpret_cast<__half2*>(&u);
}

// ---------------- stage 3: fused rel-scores + softmax + attn@V per (b,q) ----------------
__global__ void __launch_bounds__(256, 3) k_attn(
    const float* __restrict__ b_fus,
    const int* __restrict__ pos_s,
    const int* __restrict__ pos_e,
    const int* __restrict__ seq_len)
{
    __shared__ __align__(16) __half g_s[NH_][H_];    // 8 KB
    __shared__ __align__(16) float sc[NH_][L_];      // 6 KB
    __shared__ int ksp[L_], kep[L_];

    const int m = blockIdx.x;          // b*L + q
    const int b = m / L_;
    const int qi = m % L_;
    const int tid = threadIdx.x;
    const int lane = tid & 31;
    const int warp = tid >> 5;

    {
        const uint4* src = reinterpret_cast<const uint4*>(d_gh + (size_t)m * (NH_ * H_));
        uint4* dst = reinterpret_cast<uint4*>(&g_s[0][0]);
        for (int i = tid; i < (NH_ * H_) / 8; i += 256) dst[i] = src[i];
    }
    for (int i = tid; i < NH_ * L_; i += 256) {
        const int n = i / L_, k = i % L_;
        sc[n][k] = d_qk[((size_t)(b * NH_ + n) * L_ + qi) * L_ + k];
    }
    for (int i = tid; i < L_; i += 256) { ksp[i] = pos_s[b * L_ + i]; kep[i] = pos_e[b * L_ + i]; }
    const int psq = pos_s[m], peq = pos_e[m];
    const int slen = seq_len[b];

    __half2 bfh[2][4];
#pragma unroll
    for (int ci = 0; ci < 2; ++ci) {
        const int h = lane * 8 + ci * 256;
        float4 f0 = *reinterpret_cast<const float4*>(b_fus + h);
        float4 f1 = *reinterpret_cast<const float4*>(b_fus + h + 4);
        bfh[ci][0] = __floats2half2_rn(f0.x, f0.y);
        bfh[ci][1] = __floats2half2_rn(f0.z, f0.w);
        bfh[ci][2] = __floats2half2_rn(f1.x, f1.y);
        bfh[ci][3] = __floats2half2_rn(f1.z, f1.w);
    }
    __syncthreads();

    const __half2 hz = __float2half2_rn(0.f);
    const __half* __restrict__ T = d_Th;
    const int lane8 = lane << 3;

    int o0, o1, o2, o3;
    {
        const int kk0 = warp;
        o0 = ((0 * TROWS_ + psq - ksp[kk0] + 191) << 9);
        o1 = ((1 * TROWS_ + psq - kep[kk0] + 191) << 9);
        o2 = ((2 * TROWS_ + peq - ksp[kk0] + 191) << 9);
        o3 = ((3 * TROWS_ + peq - kep[kk0] + 191) << 9);
    }
    uint4 A0 = *reinterpret_cast<const uint4*>(T + o0 + lane8);
    uint4 A1 = *reinterpret_cast<const uint4*>(T + o1 + lane8);
    uint4 A2 = *reinterpret_cast<const uint4*>(T + o2 + lane8);
    uint4 A3 = *reinterpret_cast<const uint4*>(T + o3 + lane8);

    int kk = warp;
#pragma unroll 1
    for (int t = 0; t < 24; ++t) {
        __half2 acc[NH_];
#pragma unroll
        for (int n = 0; n < NH_; ++n) acc[n] = hz;

        uint4 B0 = *reinterpret_cast<const uint4*>(T + o0 + lane8 + 256);
        uint4 B1 = *reinterpret_cast<const uint4*>(T + o1 + lane8 + 256);
        uint4 B2 = *reinterpret_cast<const uint4*>(T + o2 + lane8 + 256);
        uint4 B3 = *reinterpret_cast<const uint4*>(T + o3 + lane8 + 256);

        {
            const __half2* c0 = reinterpret_cast<const __half2*>(&A0);
            const __half2* c1 = reinterpret_cast<const __half2*>(&A1);
            const __half2* c2 = reinterpret_cast<const __half2*>(&A2);
            const __half2* c3 = reinterpret_cast<const __half2*>(&A3);
            __half2 r[4];
#pragma unroll
            for (int j = 0; j < 4; ++j) {
                __half2 s = __hadd2(__hadd2(c0[j], c1[j]), __hadd2(c2[j], c3[j]));
                r[j] = __hmax2(__hadd2(s, bfh[0][j]), hz);
            }
#pragma unroll
            for (int n = 0; n < NH_; ++n) {
                uint4 gg = *reinterpret_cast<const uint4*>(&g_s[n][lane8]);
                const __half2* gh = reinterpret_cast<const __half2*>(&gg);
#pragma unroll
                for (int j = 0; j < 4; ++j) acc[n] = __hfma2(gh[j], r[j], acc[n]);
            }
        }

        if (t < 23) {
            const int kn = kk + 8;
            o0 = ((0 * TROWS_ + psq - ksp[kn] + 191) << 9);
            o1 = ((1 * TROWS_ + psq - kep[kn] + 191) << 9);
            o2 = ((2 * TROWS_ + peq - ksp[kn] + 191) << 9);
            o3 = ((3 * TROWS_ + peq - kep[kn] + 191) << 9);
            A0 = *reinterpret_cast<const uint4*>(T + o0 + lane8);
            A1 = *reinterpret_cast<const uint4*>(T + o1 + lane8);
            A2 = *reinterpret_cast<const uint4*>(T + o2 + lane8);
            A3 = *reinterpret_cast<const uint4*>(T + o3 + lane8);
        }

        {
            const __half2* c0 = reinterpret_cast<const __half2*>(&B0);
            const __half2* c1 = reinterpret_cast<const __half2*>(&B1);
            const __half2* c2 = reinterpret_cast<const __half2*>(&B2);
            const __half2* c3 = reinterpret_cast<const __half2*>(&B3);
            __half2 r[4];
#pragma unroll
            for (int j = 0; j < 4; ++j) {
                __half2 s = __hadd2(__hadd2(c0[j], c1[j]), __hadd2(c2[j], c3[j]));
                r[j] = __hmax2(__hadd2(s, bfh[1][j]), hz);
            }
#pragma unroll
            for (int n = 0; n < NH_; ++n) {
                uint4 gg = *reinterpret_cast<const uint4*>(&g_s[n][lane8 + 256]);
                const __half2* gh = reinterpret_cast<const __half2*>(&gg);
#pragma unroll
                for (int j = 0; j < 4; ++j) acc[n] = __hfma2(gh[j], r[j], acc[n]);
            }
        }

#pragma unroll
        for (int s = 16; s > 0; s >>= 1) {
#pragma unroll
            for (int n = 0; n < NH_; ++n) acc[n] = __hadd2(acc[n], shfl_xor_h2(acc[n], s));
        }
        if (lane == 0) {
            const bool valid = kk < slen;
#pragma unroll
            for (int n = 0; n < NH_; ++n) {
                float bd = __low2float(acc[n]) + __high2float(acc[n]);
                float v = (sc[n][kk] + bd) * 0.125f;
                sc[n][kk] = valid ? v : -1e30f;
            }
        }
        kk += 8;
    }
    __syncthreads();

    // softmax over k, warp = head
    {
        const int n = warp;
        float mx = -3.4e38f;
#pragma unroll
        for (int j = 0; j < 6; ++j) mx = fmaxf(mx, sc[n][lane + 32 * j]);
#pragma unroll
        for (int s = 16; s > 0; s >>= 1) mx = fmaxf(mx, __shfl_xor_sync(0xffffffffu, mx, s));
        float sum = 0.f;
        float ev[6];
#pragma unroll
        for (int j = 0; j < 6; ++j) {
            ev[j] = __expf(sc[n][lane + 32 * j] - mx);
            sum += ev[j];
        }
#pragma unroll
        for (int s = 16; s > 0; s >>= 1) sum += __shfl_xor_sync(0xffffffffu, sum, s);
        const float inv = 1.f / sum;
#pragma unroll
        for (int j = 0; j < 6; ++j) sc[n][lane + 32 * j] = ev[j] * inv;
    }
    __syncthreads();

    // out[m, h] = sum_k attn[n,k] * v_half[b,k,h]
    {
        const __half* __restrict__ vb = d_vh + (size_t)b * L_ * H_;
        const int h = tid * 2;
        const int n = warp;
        float o0a = 0.f, o1a = 0.f, o0b = 0.f, o1b = 0.f;
#pragma unroll 4
        for (int k = 0; k < L_; k += 2) {
            const float a0 = sc[n][k], a1 = sc[n][k + 1];
            __half2 v0 = *reinterpret_cast<const __half2*>(vb + (size_t)k * H_ + h);
            __half2 v1 = *reinterpret_cast<const __half2*>(vb + (size_t)(k + 1) * H_ + h);
            float2 f0 = __half22float2(v0);
            float2 f1 = __half22float2(v1);
            o0a += a0 * f0.x; o1a += a0 * f0.y;
            o0b += a1 * f1.x; o1b += a1 * f1.y;
        }
        d_attnout[(size_t)m * H_ + h]     = o0a + o0b;
        d_attnout[(size_t)m * H_ + h + 1] = o1a + o1b;
    }
}

// ---------------- stage 4: output projection, K-split x4 + atomic epilogue ----------------
__global__ void __launch_bounds__(256) k_ff(const float* __restrict__ Wff,
                                            const float* __restrict__ bff,
                                            float* __restrict__ out)
{
    const int c = blockIdx.z;          // K chunk 0..3, 128 each
    gemm_tile<true, true>(d_attnout + c * 128, H_, Wff + c * 128, H_,
                          (c == 0) ? bff : nullptr,
                          out, H_, ML_, H_, 128);
}

// ---------------- launch ----------------
extern "C" void kernel_launch(void* const* d_in, const int* in_sizes, int n_in,
                              void* d_out, int out_size)
{
    (void)n_in; (void)out_size;
    const float* key     = (const float*)d_in[0];
    const float* query   = (const float*)d_in[1];
    const float* value   = (const float*)d_in[2];
    const int*   seq_len = (const int*)d_in[3];
    const int ip = (in_sizes[4] == 1) ? 5 : 4;   // skip lex_num if present
    const int*   pos_s  = (const int*)d_in[ip + 0];
    const int*   pos_e  = (const int*)d_in[ip + 1];
    const float* pe     = (const float*)d_in[ip + 2];
    const float* W_fus  = (const float*)d_in[ip + 3];
    const float* b_fus  = (const float*)d_in[ip + 4];
    const float* Wk     = (const float*)d_in[ip + 5];
    const float* bk     = (const float*)d_in[ip + 6];
    const float* Wq     = (const float*)d_in[ip + 7];
    const float* bq     = (const float*)d_in[ip + 8];
    const float* Wv     = (const float*)d_in[ip + 9];
    const float* bv     = (const float*)d_in[ip + 10];
    const float* Wr     = (const float*)d_in[ip + 11];
    const float* br     = (const float*)d_in[ip + 12];  // constant over k under softmax -> dropped
    const float* u_bias = (const float*)d_in[ip + 13];
    const float* v_bias = (const float*)d_in[ip + 14];
    const float* Wff    = (const float*)d_in[ip + 15];
    const float* bff    = (const float*)d_in[ip + 16];
    (void)br;

    k_pre  <<<dim3(8, 6, 7), 256>>>(key, query, value, Wk, bk, Wq, bq, Wv, bv,
                                    pe, W_fus, u_bias, v_bias);
    k_gqk  <<<dim3(8, 6, 25), 256>>>(Wr, (float*)d_out);
    k_attn <<<ML_, 256>>>(b_fus, pos_s, pos_e, seq_len);
    k_ff   <<<dim3(8, 6, 4), 256>>>(Wff, bff, (float*)d_out);
}

// round 5
// speedup vs baseline: 1.2548x; 1.0959x over previous
#include <cuda_runtime.h>
#include <cuda_fp16.h>
#include <cstdint>
#include <cstddef>

#define B_    2
#define L_    192
#define H_    512
#define NH_   8
#define ML_   (B_*L_)     // 384 rows (b,l) flattened
#define TROWS_ 383        // distinct position diffs: [-191, 191]
#define SCP_  196         // padded score row (bank-conflict-free 8-lane stores)

// ---------------- scratch (device globals; no allocation allowed) ----------------
static __device__ __align__(16) __half d_Th[4 * TROWS_ * H_];   // 4 pe tables (half; T0 includes b_fus)
static __device__ __align__(16) float  d_kproj[ML_ * H_];
static __device__ __align__(16) float  d_qkA[ML_ * H_];         // qproj + bq + u_bias
static __device__ __align__(16) float  d_u[ML_ * H_];           // qproj + bq + v_bias
static __device__ __align__(16) __half d_vh[ML_ * H_];          // v projection (half)
static __device__ __align__(16) __half d_gh[ML_ * NH_ * H_];    // u_head @ Wr_head (half)
static __device__ __align__(16) float  d_qk[2 * NH_ * L_ * L_]; // per-head (q+u_bias).k
static __device__ __align__(16) float  d_attnout[ML_ * H_];

__device__ __forceinline__ float st_conv(float v, float*)  { return v; }
__device__ __forceinline__ __half st_conv(float v, __half*) { return __float2half(v); }

// ------- tiled SGEMM: 64x64 tile, BK=16, 4x4 microtile, DOUBLE-BUFFERED smem -------
template<bool TRANSB, bool ATOMIC, typename OT>
__device__ __forceinline__ void gemm_tile(
    const float* __restrict__ A, int lda,
    const float* __restrict__ B, int ldb,
    const float* __restrict__ bias,
    OT* __restrict__ C, int ldc,
    int M, int N, int K,
    const float* __restrict__ addA = nullptr,
    float* __restrict__ C2 = nullptr,
    const float* __restrict__ add2 = nullptr)
{
    __shared__ float As[2][16][68];
    __shared__ float Bs[2][16][68];
    const int tid = threadIdx.x;
    const int tx = tid & 15, ty = tid >> 4;
    const int m0 = blockIdx.y * 64, n0 = blockIdx.x * 64;
    float acc[4][4];
#pragma unroll
    for (int i = 0; i < 4; ++i)
#pragma unroll
        for (int j = 0; j < 4; ++j) acc[i][j] = 0.f;

    const int lm = tid >> 2;          // 0..63
    const int lk = (tid & 3) * 4;     // 0,4,8,12
    const int bk = tid >> 4;          // 0..15 (NN B)
    const int bn = (tid & 15) * 4;    // 0..60

    {
        float4 av = make_float4(0.f, 0.f, 0.f, 0.f);
        if (m0 + lm < M)
            av = *reinterpret_cast<const float4*>(A + (size_t)(m0 + lm) * lda + lk);
        As[0][lk + 0][lm] = av.x; As[0][lk + 1][lm] = av.y;
        As[0][lk + 2][lm] = av.z; As[0][lk + 3][lm] = av.w;
        if (TRANSB) {
            float4 bv = make_float4(0.f, 0.f, 0.f, 0.f);
            if (n0 + lm < N)
                bv = *reinterpret_cast<const float4*>(B + (size_t)(n0 + lm) * ldb + lk);
            Bs[0][lk + 0][lm] = bv.x; Bs[0][lk + 1][lm] = bv.y;
            Bs[0][lk + 2][lm] = bv.z; Bs[0][lk + 3][lm] = bv.w;
        } else {
            float4 bv = make_float4(0.f, 0.f, 0.f, 0.f);
            if (n0 + bn < N)
                bv = *reinterpret_cast<const float4*>(B + (size_t)bk * ldb + n0 + bn);
            *reinterpret_cast<float4*>(&Bs[0][bk][bn]) = bv;
        }
    }
    __syncthreads();

    int buf = 0;
    for (int k0 = 0; k0 < K; k0 += 16) {
        const bool has_next = (k0 + 16 < K);
        float4 av = make_float4(0.f, 0.f, 0.f, 0.f);
        float4 bv = make_float4(0.f, 0.f, 0.f, 0.f);
        if (has_next) {
            const int kn = k0 + 16;
            if (m0 + lm < M)
                av = *reinterpret_cast<const float4*>(A + (size_t)(m0 + lm) * lda + kn + lk);
            if (TRANSB) {
                if (n0 + lm < N)
                    bv = *reinterpret_cast<const float4*>(B + (size_t)(n0 + lm) * ldb + kn + lk);
            } else {
                if (n0 + bn < N)
                    bv = *reinterpret_cast<const float4*>(B + (size_t)(kn + bk) * ldb + n0 + bn);
            }
        }
#pragma unroll
        for (int kk = 0; kk < 16; ++kk) {
            float a[4], bb[4];
#pragma unroll
            for (int i = 0; i < 4; ++i) a[i] = As[buf][kk][ty * 4 + i];
#pragma unroll
            for (int j = 0; j < 4; ++j) bb[j] = Bs[buf][kk][tx * 4 + j];
#pragma unroll
            for (int i = 0; i < 4; ++i)
#pragma unroll
                for (int j = 0; j < 4; ++j) acc[i][j] += a[i] * bb[j];
        }
        if (has_next) {
            const int nb = buf ^ 1;
            As[nb][lk + 0][lm] = av.x; As[nb][lk + 1][lm] = av.y;
            As[nb][lk + 2][lm] = av.z; As[nb][lk + 3][lm] = av.w;
            if (TRANSB) {
                Bs[nb][lk + 0][lm] = bv.x; Bs[nb][lk + 1][lm] = bv.y;
                Bs[nb][lk + 2][lm] = bv.z; Bs[nb][lk + 3][lm] = bv.w;
            } else {
                *reinterpret_cast<float4*>(&Bs[nb][bk][bn]) = bv;
            }
        }
        __syncthreads();
        buf ^= 1;
    }

    const int mo = m0 + ty * 4, no = n0 + tx * 4;
#pragma unroll
    for (int i = 0; i < 4; ++i) {
        if (mo + i < M) {
#pragma unroll
            for (int j = 0; j < 4; ++j) {
                if (no + j < N) {
                    float base = acc[i][j];
                    if (bias) base += bias[no + j];
                    if (ATOMIC) {
                        atomicAdd(reinterpret_cast<float*>(&C[(size_t)(mo + i) * ldc + no + j]), base);
                    } else {
                        float v1 = base;
                        if (addA) v1 += addA[no + j];
                        C[(size_t)(mo + i) * ldc + no + j] = st_conv(v1, (OT*)nullptr);
                        if (C2) C2[(size_t)(mo + i) * ldc + no + j] = base + add2[no + j];
                    }
                }
            }
        }
    }
}

// ---------------- stage 1: projections + pe tables (fused launch) ----------------
__global__ void __launch_bounds__(256) k_pre(
    const float* __restrict__ key, const float* __restrict__ query, const float* __restrict__ value,
    const float* __restrict__ Wk, const float* __restrict__ bk,
    const float* __restrict__ Wq, const float* __restrict__ bq,
    const float* __restrict__ Wv, const float* __restrict__ bv,
    const float* __restrict__ pe, const float* __restrict__ W_fus,
    const float* __restrict__ b_fus,
    const float* __restrict__ u_bias, const float* __restrict__ v_bias)
{
    const int z = blockIdx.z;
    if (z == 0) {
        gemm_tile<true, false>(key, H_, Wk, H_, bk, d_kproj, H_, ML_, H_, H_);
    } else if (z == 1) {
        gemm_tile<true, false>(query, H_, Wq, H_, bq, d_qkA, H_, ML_, H_, H_,
                               u_bias, d_u, v_bias);
    } else if (z == 2) {
        gemm_tile<true, false>(value, H_, Wv, H_, bv, d_vh, H_, ML_, H_, H_);
    } else {
        const int t = z - 3;   // table 0..3; b_fus folded into T0
        gemm_tile<true, false>(pe + 321 * H_, H_, W_fus + t * 256, 2 * H_,
                               (t == 0) ? b_fus : nullptr,
                               d_Th + (size_t)t * TROWS_ * H_, H_, TROWS_, H_, 256);
    }
}

// -------- stage 2: g (half) + per-head qk GEMMs + early zero of d_out --------
__global__ void __launch_bounds__(256) k_gqk(const float* __restrict__ Wr,
                                             float* __restrict__ out)
{
    const int z = blockIdx.z;
    if (z < 8) {
        gemm_tile<false, false>(d_u + z * 64, H_, Wr + (size_t)z * 64 * H_, H_, nullptr,
                                d_gh + (size_t)z * H_, NH_ * H_, ML_, H_, 64);
    } else if (z < 24) {
        if (blockIdx.x >= 3 || blockIdx.y >= 3) return;
        const int idx = z - 8;         // b*8 + n
        const int b = idx >> 3, n = idx & 7;
        gemm_tile<true, false>(d_qkA   + (size_t)b * L_ * H_ + n * 64, H_,
                               d_kproj + (size_t)b * L_ * H_ + n * 64, H_, nullptr,
                               d_qk + (size_t)idx * L_ * L_, L_, L_, L_, 64);
    } else {
        const float4 z4 = make_float4(0.f, 0.f, 0.f, 0.f);
        float4* o4 = reinterpret_cast<float4*>(out);
        const int stride = 48 * 256;
        const int start = (blockIdx.y * 8 + blockIdx.x) * 256 + threadIdx.x;
        for (int i = start; i < (ML_ * H_) / 4; i += stride) o4[i] = z4;
    }
}

__device__ __forceinline__ __half2 shfl_xor_h2(__half2 v, int s) {
    unsigned u = *reinterpret_cast<unsigned*>(&v);
    u = __shfl_xor_sync(0xffffffffu, u, s);
    return *reinterpret_cast<__half2*>(&u);
}

// ---------------- stage 3: fused rel-scores + softmax + attn@V per (b,q) ----------------
__global__ void __launch_bounds__(256, 3) k_attn(
    const int* __restrict__ pos_s,
    const int* __restrict__ pos_e,
    const int* __restrict__ seq_len)
{
    __shared__ __align__(16) __half g_s[NH_][H_];    // 8 KB
    __shared__ __align__(16) float sc[NH_][SCP_];    // padded: 8-lane stores conflict-free
    __shared__ int ksp[L_], kep[L_];

    const int m = blockIdx.x;          // b*L + q
    const int b = m / L_;
    const int qi = m % L_;
    const int tid = threadIdx.x;
    const int lane = tid & 31;
    const int warp = tid >> 5;

    {
        const uint4* src = reinterpret_cast<const uint4*>(d_gh + (size_t)m * (NH_ * H_));
        uint4* dst = reinterpret_cast<uint4*>(&g_s[0][0]);
        for (int i = tid; i < (NH_ * H_) / 8; i += 256) dst[i] = src[i];
    }
    for (int i = tid; i < NH_ * L_; i += 256) {
        const int n = i / L_, k = i % L_;
        sc[n][k] = d_qk[((size_t)(b * NH_ + n) * L_ + qi) * L_ + k];
    }
    for (int i = tid; i < L_; i += 256) { ksp[i] = pos_s[b * L_ + i]; kep[i] = pos_e[b * L_ + i]; }
    const int psq = pos_s[m], peq = pos_e[m];
    const int slen = seq_len[b];
    __syncthreads();

    const __half2 hz = __float2half2_rn(0.f);
    const __half* __restrict__ T = d_Th;
    const int lane8 = lane << 3;

    int o0, o1, o2, o3;
    {
        const int kk0 = warp;
        o0 = ((0 * TROWS_ + psq - ksp[kk0] + 191) << 9);
        o1 = ((1 * TROWS_ + psq - kep[kk0] + 191) << 9);
        o2 = ((2 * TROWS_ + peq - ksp[kk0] + 191) << 9);
        o3 = ((3 * TROWS_ + peq - kep[kk0] + 191) << 9);
    }
    uint4 A0 = *reinterpret_cast<const uint4*>(T + o0 + lane8);
    uint4 A1 = *reinterpret_cast<const uint4*>(T + o1 + lane8);
    uint4 A2 = *reinterpret_cast<const uint4*>(T + o2 + lane8);
    uint4 A3 = *reinterpret_cast<const uint4*>(T + o3 + lane8);

    int kk = warp;
#pragma unroll 1
    for (int t = 0; t < 24; ++t) {
        __half2 acc[NH_];
#pragma unroll
        for (int n = 0; n < NH_; ++n) acc[n] = hz;

        uint4 B0 = *reinterpret_cast<const uint4*>(T + o0 + lane8 + 256);
        uint4 B1 = *reinterpret_cast<const uint4*>(T + o1 + lane8 + 256);
        uint4 B2 = *reinterpret_cast<const uint4*>(T + o2 + lane8 + 256);
        uint4 B3 = *reinterpret_cast<const uint4*>(T + o3 + lane8 + 256);

        {
            const __half2* c0 = reinterpret_cast<const __half2*>(&A0);
            const __half2* c1 = reinterpret_cast<const __half2*>(&A1);
            const __half2* c2 = reinterpret_cast<const __half2*>(&A2);
            const __half2* c3 = reinterpret_cast<const __half2*>(&A3);
            __half2 r[4];
#pragma unroll
            for (int j = 0; j < 4; ++j) {
                __half2 s = __hadd2(__hadd2(c0[j], c1[j]), __hadd2(c2[j], c3[j]));
                r[j] = __hmax2(s, hz);   // b_fus folded into T0
            }
#pragma unroll
            for (int n = 0; n < NH_; ++n) {
                uint4 gg = *reinterpret_cast<const uint4*>(&g_s[n][lane8]);
                const __half2* gh = reinterpret_cast<const __half2*>(&gg);
#pragma unroll
                for (int j = 0; j < 4; ++j) acc[n] = __hfma2(gh[j], r[j], acc[n]);
            }
        }

        if (t < 23) {
            const int kn = kk + 8;
            o0 = ((0 * TROWS_ + psq - ksp[kn] + 191) << 9);
            o1 = ((1 * TROWS_ + psq - kep[kn] + 191) << 9);
            o2 = ((2 * TROWS_ + peq - ksp[kn] + 191) << 9);
            o3 = ((3 * TROWS_ + peq - kep[kn] + 191) << 9);
            A0 = *reinterpret_cast<const uint4*>(T + o0 + lane8);
            A1 = *reinterpret_cast<const uint4*>(T + o1 + lane8);
            A2 = *reinterpret_cast<const uint4*>(T + o2 + lane8);
            A3 = *reinterpret_cast<const uint4*>(T + o3 + lane8);
        }

        {
            const __half2* c0 = reinterpret_cast<const __half2*>(&B0);
            const __half2* c1 = reinterpret_cast<const __half2*>(&B1);
            const __half2* c2 = reinterpret_cast<const __half2*>(&B2);
            const __half2* c3 = reinterpret_cast<const __half2*>(&B3);
            __half2 r[4];
#pragma unroll
            for (int j = 0; j < 4; ++j) {
                __half2 s = __hadd2(__hadd2(c0[j], c1[j]), __hadd2(c2[j], c3[j]));
                r[j] = __hmax2(s, hz);
            }
#pragma unroll
            for (int n = 0; n < NH_; ++n) {
                uint4 gg = *reinterpret_cast<const uint4*>(&g_s[n][lane8 + 256]);
                const __half2* gh = reinterpret_cast<const __half2*>(&gg);
#pragma unroll
                for (int j = 0; j < 4; ++j) acc[n] = __hfma2(gh[j], r[j], acc[n]);
            }
        }

        // ---- folded reduction: 8 h2 -> 1 h2/lane, head = lane>>2 at lane%4==0 ----
        __half2 res[4];
#pragma unroll
        for (int n = 0; n < 4; ++n) {
            __half2 snd = (lane < 16) ? acc[n + 4] : acc[n];
            __half2 kp  = (lane < 16) ? acc[n]     : acc[n + 4];
            res[n] = __hadd2(kp, shfl_xor_h2(snd, 16));
        }
        __half2 r2[2];
#pragma unroll
        for (int n = 0; n < 2; ++n) {
            __half2 snd = ((lane & 8) == 0) ? res[n + 2] : res[n];
            __half2 kp  = ((lane & 8) == 0) ? res[n]     : res[n + 2];
            r2[n] = __hadd2(kp, shfl_xor_h2(snd, 8));
        }
        __half2 fin;
        {
            __half2 snd = ((lane & 4) == 0) ? r2[1] : r2[0];
            __half2 kp  = ((lane & 4) == 0) ? r2[0] : r2[1];
            fin = __hadd2(kp, shfl_xor_h2(snd, 4));
        }
        fin = __hadd2(fin, shfl_xor_h2(fin, 2));
        fin = __hadd2(fin, shfl_xor_h2(fin, 1));
        if ((lane & 3) == 0) {
            const int n = lane >> 2;
            float bd = __low2float(fin) + __high2float(fin);
            float v = (sc[n][kk] + bd) * 0.125f;
            sc[n][kk] = (kk < slen) ? v : -1e30f;
        }
        kk += 8;
    }
    __syncthreads();

    // softmax over k, warp = head
    {
        const int n = warp;
        float mx = -3.4e38f;
#pragma unroll
        for (int j = 0; j < 6; ++j) mx = fmaxf(mx, sc[n][lane + 32 * j]);
#pragma unroll
        for (int s = 16; s > 0; s >>= 1) mx = fmaxf(mx, __shfl_xor_sync(0xffffffffu, mx, s));
        float sum = 0.f;
        float ev[6];
#pragma unroll
        for (int j = 0; j < 6; ++j) {
            ev[j] = __expf(sc[n][lane + 32 * j] - mx);
            sum += ev[j];
        }
#pragma unroll
        for (int s = 16; s > 0; s >>= 1) sum += __shfl_xor_sync(0xffffffffu, sum, s);
        const float inv = 1.f / sum;
#pragma unroll
        for (int j = 0; j < 6; ++j) sc[n][lane + 32 * j] = ev[j] * inv;
    }
    __syncwarp();   // head-n softmax and head-n AV are the same warp: no block sync needed

    // out[m, h] = sum_k attn[n,k] * v_half[b,k,h]   (n = warp for h = 2*tid)
    {
        const __half* __restrict__ vb = d_vh + (size_t)b * L_ * H_;
        const int h = tid * 2;
        const int n = warp;
        float oa = 0.f, ob = 0.f, oc = 0.f, od = 0.f;
        float pa = 0.f, pb = 0.f, pc = 0.f, pd = 0.f;
#pragma unroll 2
        for (int k = 0; k < L_; k += 4) {
            const float a0 = sc[n][k],     a1 = sc[n][k + 1];
            const float a2 = sc[n][k + 2], a3 = sc[n][k + 3];
            __half2 v0 = *reinterpret_cast<const __half2*>(vb + (size_t)k * H_ + h);
            __half2 v1 = *reinterpret_cast<const __half2*>(vb + (size_t)(k + 1) * H_ + h);
            __half2 v2 = *reinterpret_cast<const __half2*>(vb + (size_t)(k + 2) * H_ + h);
            __half2 v3 = *reinterpret_cast<const __half2*>(vb + (size_t)(k + 3) * H_ + h);
            float2 f0 = __half22float2(v0);
            float2 f1 = __half22float2(v1);
            float2 f2 = __half22float2(v2);
            float2 f3 = __half22float2(v3);
            oa += a0 * f0.x; pa += a0 * f0.y;
            ob += a1 * f1.x; pb += a1 * f1.y;
            oc += a2 * f2.x; pc += a2 * f2.y;
            od += a3 * f3.x; pd += a3 * f3.y;
        }
        d_attnout[(size_t)m * H_ + h]     = (oa + ob) + (oc + od);
        d_attnout[(size_t)m * H_ + h + 1] = (pa + pb) + (pc + pd);
    }
}

// ---------------- stage 4: output projection, K-split x8 + atomic epilogue ----------------
__global__ void __launch_bounds__(256) k_ff(const float* __restrict__ Wff,
                                            const float* __restrict__ bff,
                                            float* __restrict__ out)
{
    const int c = blockIdx.z;          // K chunk 0..7, 64 each
    gemm_tile<true, true>(d_attnout + c * 64, H_, Wff + c * 64, H_,
                          (c == 0) ? bff : nullptr,
                          out, H_, ML_, H_, 64);
}

// ---------------- launch ----------------
extern "C" void kernel_launch(void* const* d_in, const int* in_sizes, int n_in,
                              void* d_out, int out_size)
{
    (void)n_in; (void)out_size;
    const float* key     = (const float*)d_in[0];
    const float* query   = (const float*)d_in[1];
    const float* value   = (const float*)d_in[2];
    const int*   seq_len = (const int*)d_in[3];
    const int ip = (in_sizes[4] == 1) ? 5 : 4;   // skip lex_num if present
    const int*   pos_s  = (const int*)d_in[ip + 0];
    const int*   pos_e  = (const int*)d_in[ip + 1];
    const float* pe     = (const float*)d_in[ip + 2];
    const float* W_fus  = (const float*)d_in[ip + 3];
    const float* b_fus  = (const float*)d_in[ip + 4];
    const float* Wk     = (const float*)d_in[ip + 5];
    const float* bk     = (const float*)d_in[ip + 6];
    const float* Wq     = (const float*)d_in[ip + 7];
    const float* bq     = (const float*)d_in[ip + 8];
    const float* Wv     = (const float*)d_in[ip + 9];
    const float* bv     = (const float*)d_in[ip + 10];
    const float* Wr     = (const float*)d_in[ip + 11];
    const float* br     = (const float*)d_in[ip + 12];  // constant over k under softmax -> dropped
    const float* u_bias = (const float*)d_in[ip + 13];
    const float* v_bias = (const float*)d_in[ip + 14];
    const float* Wff    = (const float*)d_in[ip + 15];
    const float* bff    = (const float*)d_in[ip + 16];
    (void)br;

    k_pre  <<<dim3(8, 6, 7), 256>>>(key, query, value, Wk, bk, Wq, bq, Wv, bv,
                                    pe, W_fus, b_fus, u_bias, v_bias);
    k_gqk  <<<dim3(8, 6, 25), 256>>>(Wr, (float*)d_out);
    k_attn <<<ML_, 256>>>(pos_s, pos_e, seq_len);
    k_ff   <<<dim3(8, 6, 8), 256>>>(Wff, bff, (float*)d_out);
}